// round 1
// baseline (speedup 1.0000x reference)
#include <cuda_runtime.h>
#include <math.h>

#define S_        8192
#define HID_      1280
#define H_        16
#define D_        80
#define C_        8
#define L_        1024
#define THREE_HID 3840

// Scratch (allocation-free rule: __device__ globals)
__device__ float g_qkv[(size_t)S_ * THREE_HID];   // 126 MB
__device__ float g_q[(size_t)H_ * S_ * D_];       // 40 MB, [H][S][D]
__device__ float g_k[(size_t)H_ * S_ * D_];
__device__ float g_v[(size_t)H_ * S_ * D_];
__device__ float g_attn[(size_t)S_ * HID_];       // 40 MB, [S][HID]

// ---------------------------------------------------------------------------
// Classic fp32 SGEMM: C[M,N] = A[M,K] @ B[K,N] + bias[N]
// BM=BN=128, BK=8, TM=TN=8, 256 threads. All dims divide evenly here.
// ---------------------------------------------------------------------------
__global__ __launch_bounds__(256) void sgemm_bias(
    const float* __restrict__ A, const float* __restrict__ B,
    const float* __restrict__ bias, float* __restrict__ Cm,
    int M, int N, int K)
{
    __shared__ float As[8][128];
    __shared__ float Bs[8][128];

    const int tid = threadIdx.x;
    const int bx = blockIdx.x, by = blockIdx.y;

    const int aRow = tid >> 1;          // 0..127
    const int aCol = (tid & 1) * 4;     // 0 or 4
    const int bRow = tid >> 5;          // 0..7
    const int bCol = (tid & 31) * 4;    // 0..124
    const int tx = tid & 15, ty = tid >> 4;

    float acc[8][8];
#pragma unroll
    for (int i = 0; i < 8; i++)
#pragma unroll
        for (int j = 0; j < 8; j++) acc[i][j] = 0.f;

    const float* Aptr = A + (size_t)(by * 128 + aRow) * K + aCol;
    const float* Bptr = B + (size_t)bRow * N + bx * 128 + bCol;

    for (int k0 = 0; k0 < K; k0 += 8) {
        float4 av = *(const float4*)(Aptr + k0);
        As[aCol + 0][aRow] = av.x;
        As[aCol + 1][aRow] = av.y;
        As[aCol + 2][aRow] = av.z;
        As[aCol + 3][aRow] = av.w;
        *(float4*)&Bs[bRow][bCol] = *(const float4*)(Bptr + (size_t)k0 * N);
        __syncthreads();

#pragma unroll
        for (int kk = 0; kk < 8; kk++) {
            float4 a0 = *(const float4*)&As[kk][ty * 8];
            float4 a1 = *(const float4*)&As[kk][ty * 8 + 4];
            float4 b0 = *(const float4*)&Bs[kk][tx * 8];
            float4 b1 = *(const float4*)&Bs[kk][tx * 8 + 4];
            float ra[8] = {a0.x, a0.y, a0.z, a0.w, a1.x, a1.y, a1.z, a1.w};
            float rb[8] = {b0.x, b0.y, b0.z, b0.w, b1.x, b1.y, b1.z, b1.w};
#pragma unroll
            for (int i = 0; i < 8; i++)
#pragma unroll
                for (int j = 0; j < 8; j++)
                    acc[i][j] += ra[i] * rb[j];
        }
        __syncthreads();
    }

#pragma unroll
    for (int i = 0; i < 8; i++) {
        int row = by * 128 + ty * 8 + i;
#pragma unroll
        for (int j = 0; j < 8; j += 4) {
            int col = bx * 128 + tx * 8 + j;
            float4 o;
            o.x = acc[i][j + 0] + bias[col + 0];
            o.y = acc[i][j + 1] + bias[col + 1];
            o.z = acc[i][j + 2] + bias[col + 2];
            o.w = acc[i][j + 3] + bias[col + 3];
            *(float4*)(Cm + (size_t)row * N + col) = o;
        }
    }
}

// ---------------------------------------------------------------------------
// RoPE + split qkv[S,3*HID] -> q,k (rotated), v in [H][S][D] layout
// ---------------------------------------------------------------------------
__global__ void rope_split(const float* __restrict__ cosp,
                           const float* __restrict__ sinp)
{
    int idx = blockIdx.x * blockDim.x + threadIdx.x;
    if (idx >= S_ * HID_) return;
    int s   = idx / HID_;
    int col = idx - s * HID_;
    int h   = col / D_;
    int d   = col - h * D_;

    const float* base = g_qkv + (size_t)s * THREE_HID;
    float qv = base[col];
    float kv = base[HID_ + col];
    float vv = base[2 * HID_ + col];

    float c  = cosp[s * D_ + d];
    float sn = sinp[s * D_ + d];

    int off = (d < 40) ? (col + 40) : (col - 40);
    float sgn = (d < 40) ? -1.f : 1.f;
    float qrot = sgn * base[off];
    float krot = sgn * base[HID_ + off];

    size_t o = (size_t)h * S_ * D_ + (size_t)s * D_ + d;
    g_q[o] = qv * c + qrot * sn;
    g_k[o] = kv * c + krot * sn;
    g_v[o] = vv;
}

// ---------------------------------------------------------------------------
// Flash-style attention. 1 block = (chunk c, head h, 32 q-rows).
// 256 threads = 32 rows x 8 lanes; each thread owns 10 output dims.
// Online softmax state (m, l) kept redundantly in registers across the 8-lane
// group (coherent via butterfly shuffles). Smem strides padded (84 / 33) for
// conflict-free LDS.
// ---------------------------------------------------------------------------
__global__ __launch_bounds__(256) void attn_kernel()
{
    __shared__ float sQ[32][84];
    __shared__ float sK[32][84];
    __shared__ float sV[32][84];
    __shared__ float sP[32][33];

    const int bx = blockIdx.x;
    const int qt = bx & 31;
    const int h  = (bx >> 5) & 15;
    const int c  = bx >> 9;

    const int tid = threadIdx.x;
    const int r = tid >> 3;   // q-row within tile (0..31)
    const int u = tid & 7;    // lane within row group (0..7)

    const float* qbase = g_q + (size_t)h * S_ * D_ + (size_t)(c * L_ + qt * 32) * D_;
    const float* kbase = g_k + (size_t)h * S_ * D_ + (size_t)(c * L_) * D_;
    const float* vbase = g_v + (size_t)h * S_ * D_ + (size_t)(c * L_) * D_;

    for (int i = tid; i < 32 * 80; i += 256)
        sQ[i / 80][i % 80] = qbase[i];

    float m = -1e30f, l = 0.f;
    float acc[10];
#pragma unroll
    for (int i = 0; i < 10; i++) acc[i] = 0.f;
    const float inv_scale = rsqrtf((float)D_);
    __syncthreads();

    for (int j0 = 0; j0 < L_; j0 += 32) {
        for (int i = tid; i < 32 * 80; i += 256) {
            int rr = i / 80, dd = i % 80;
            sK[rr][dd] = kbase[j0 * 80 + i];
            sV[rr][dd] = vbase[j0 * 80 + i];
        }
        __syncthreads();

        // scores: thread (r,u) computes j = u, u+8, u+16, u+24
        float a0 = 0.f, a1 = 0.f, a2 = 0.f, a3 = 0.f;
#pragma unroll
        for (int d = 0; d < 80; d++) {
            float qd = sQ[r][d];
            a0 += qd * sK[u][d];
            a1 += qd * sK[u + 8][d];
            a2 += qd * sK[u + 16][d];
            a3 += qd * sK[u + 24][d];
        }
        a0 *= inv_scale; a1 *= inv_scale; a2 *= inv_scale; a3 *= inv_scale;

        // online softmax across the 8-lane group (shuffle reductions)
        float tmax = fmaxf(fmaxf(a0, a1), fmaxf(a2, a3));
#pragma unroll
        for (int o = 1; o < 8; o <<= 1)
            tmax = fmaxf(tmax, __shfl_xor_sync(0xffffffffu, tmax, o));
        float newm = fmaxf(m, tmax);
        float p0 = __expf(a0 - newm);
        float p1 = __expf(a1 - newm);
        float p2 = __expf(a2 - newm);
        float p3 = __expf(a3 - newm);
        float sum = p0 + p1 + p2 + p3;
#pragma unroll
        for (int o = 1; o < 8; o <<= 1)
            sum += __shfl_xor_sync(0xffffffffu, sum, o);
        float corr = __expf(m - newm);
        l = l * corr + sum;
        m = newm;

        sP[r][u]      = p0;
        sP[r][u + 8]  = p1;
        sP[r][u + 16] = p2;
        sP[r][u + 24] = p3;
        __syncwarp();   // sP[r][*] produced/consumed by the same warp

        // accumulate: acc[d-slice] += P-tile @ V-tile
#pragma unroll
        for (int i = 0; i < 10; i++) acc[i] *= corr;
#pragma unroll
        for (int jj = 0; jj < 32; jj++) {
            float p = sP[r][jj];
#pragma unroll
            for (int i = 0; i < 10; i++)
                acc[i] += p * sV[jj][u * 10 + i];
        }
        __syncthreads();   // before next tile overwrites sK/sV
    }

    float invl = 1.f / l;
    int srow = c * L_ + qt * 32 + r;
    float* outp = g_attn + (size_t)srow * HID_ + h * D_ + u * 10;
#pragma unroll
    for (int i = 0; i < 10; i++)
        outp[i] = acc[i] * invl;
}

// ---------------------------------------------------------------------------
// Launch: qkv gemm -> rope/split -> attention -> proj gemm
// Inputs (metadata order): x, cos, sin, Wqkv, bqkv, Wproj, bproj, cu_seqlens
// ---------------------------------------------------------------------------
extern "C" void kernel_launch(void* const* d_in, const int* in_sizes, int n_in,
                              void* d_out, int out_size)
{
    const float* x     = (const float*)d_in[0];
    const float* cosp  = (const float*)d_in[1];
    const float* sinp  = (const float*)d_in[2];
    const float* Wqkv  = (const float*)d_in[3];
    const float* bqkv  = (const float*)d_in[4];
    const float* Wproj = (const float*)d_in[5];
    const float* bproj = (const float*)d_in[6];
    float* out = (float*)d_out;

    float *qkv_p, *attn_p;
    cudaGetSymbolAddress((void**)&qkv_p, g_qkv);
    cudaGetSymbolAddress((void**)&attn_p, g_attn);

    dim3 g1(THREE_HID / 128, S_ / 128);
    sgemm_bias<<<g1, 256>>>(x, Wqkv, bqkv, qkv_p, S_, THREE_HID, HID_);

    rope_split<<<(S_ * HID_ + 255) / 256, 256>>>(cosp, sinp);

    attn_kernel<<<C_ * H_ * (L_ / 32), 256>>>();

    dim3 g2(HID_ / 128, S_ / 128);
    sgemm_bias<<<g2, 256>>>(attn_p, Wproj, bproj, out, S_, HID_, HID_);
}

// round 2
// speedup vs baseline: 1.1862x; 1.1862x over previous
#include <cuda_runtime.h>
#include <math.h>

#define S_        8192
#define HID_      1280
#define H_        16
#define D_        80
#define C_        8
#define L_        1024
#define THREE_HID 3840

// Scratch (allocation-free rule: __device__ globals)
__device__ float g_qkv[(size_t)S_ * THREE_HID];   // 126 MB
__device__ float g_q[(size_t)H_ * S_ * D_];       // 40 MB, [H][S][D]
__device__ float g_k[(size_t)H_ * S_ * D_];
__device__ float g_v[(size_t)H_ * S_ * D_];
__device__ float g_attn[(size_t)S_ * HID_];       // 40 MB, [S][HID]

// ---------------------------------------------------------------------------
// Classic fp32 SGEMM: C[M,N] = A[M,K] @ B[K,N] + bias[N]
// BM=BN=128, BK=8, TM=TN=8, 256 threads.
// ---------------------------------------------------------------------------
__global__ __launch_bounds__(256) void sgemm_bias(
    const float* __restrict__ A, const float* __restrict__ B,
    const float* __restrict__ bias, float* __restrict__ Cm,
    int M, int N, int K)
{
    __shared__ float As[8][128];
    __shared__ float Bs[8][128];

    const int tid = threadIdx.x;
    const int bx = blockIdx.x, by = blockIdx.y;

    const int aRow = tid >> 1;
    const int aCol = (tid & 1) * 4;
    const int bRow = tid >> 5;
    const int bCol = (tid & 31) * 4;
    const int tx = tid & 15, ty = tid >> 4;

    float acc[8][8];
#pragma unroll
    for (int i = 0; i < 8; i++)
#pragma unroll
        for (int j = 0; j < 8; j++) acc[i][j] = 0.f;

    const float* Aptr = A + (size_t)(by * 128 + aRow) * K + aCol;
    const float* Bptr = B + (size_t)bRow * N + bx * 128 + bCol;

    for (int k0 = 0; k0 < K; k0 += 8) {
        float4 av = *(const float4*)(Aptr + k0);
        As[aCol + 0][aRow] = av.x;
        As[aCol + 1][aRow] = av.y;
        As[aCol + 2][aRow] = av.z;
        As[aCol + 3][aRow] = av.w;
        *(float4*)&Bs[bRow][bCol] = *(const float4*)(Bptr + (size_t)k0 * N);
        __syncthreads();

#pragma unroll
        for (int kk = 0; kk < 8; kk++) {
            float4 a0 = *(const float4*)&As[kk][ty * 8];
            float4 a1 = *(const float4*)&As[kk][ty * 8 + 4];
            float4 b0 = *(const float4*)&Bs[kk][tx * 8];
            float4 b1 = *(const float4*)&Bs[kk][tx * 8 + 4];
            float ra[8] = {a0.x, a0.y, a0.z, a0.w, a1.x, a1.y, a1.z, a1.w};
            float rb[8] = {b0.x, b0.y, b0.z, b0.w, b1.x, b1.y, b1.z, b1.w};
#pragma unroll
            for (int i = 0; i < 8; i++)
#pragma unroll
                for (int j = 0; j < 8; j++)
                    acc[i][j] += ra[i] * rb[j];
        }
        __syncthreads();
    }

#pragma unroll
    for (int i = 0; i < 8; i++) {
        int row = by * 128 + ty * 8 + i;
#pragma unroll
        for (int j = 0; j < 8; j += 4) {
            int col = bx * 128 + tx * 8 + j;
            float4 o;
            o.x = acc[i][j + 0] + bias[col + 0];
            o.y = acc[i][j + 1] + bias[col + 1];
            o.z = acc[i][j + 2] + bias[col + 2];
            o.w = acc[i][j + 3] + bias[col + 3];
            *(float4*)(Cm + (size_t)row * N + col) = o;
        }
    }
}

// ---------------------------------------------------------------------------
// RoPE + split qkv[S,3*HID] -> q,k (rotated), v in [H][S][D] layout
// ---------------------------------------------------------------------------
__global__ void rope_split(const float* __restrict__ cosp,
                           const float* __restrict__ sinp)
{
    int idx = blockIdx.x * blockDim.x + threadIdx.x;
    if (idx >= S_ * HID_) return;
    int s   = idx / HID_;
    int col = idx - s * HID_;
    int h   = col / D_;
    int d   = col - h * D_;

    const float* base = g_qkv + (size_t)s * THREE_HID;
    float qv = base[col];
    float kv = base[HID_ + col];
    float vv = base[2 * HID_ + col];

    float c  = cosp[s * D_ + d];
    float sn = sinp[s * D_ + d];

    int off = (d < 40) ? (col + 40) : (col - 40);
    float sgn = (d < 40) ? -1.f : 1.f;
    float qrot = sgn * base[off];
    float krot = sgn * base[HID_ + off];

    size_t o = (size_t)h * S_ * D_ + (size_t)s * D_ + d;
    g_q[o] = qv * c + qrot * sn;
    g_k[o] = kv * c + krot * sn;
    g_v[o] = vv;
}

// ---------------------------------------------------------------------------
// Register-tiled flash attention.
// 1 block = (chunk c, head h, 64 q-rows). 256 threads.
// Score phase: thread (ty,tx) owns a 4x4 tile of S (rows ty*4.., cols tx*4..),
//   fed by transposed smem (sQt[d][row], sKt[d][col]) -> 2 LDS.128 / 16 FFMA.
// PV phase: thread owns (1 row x 20 cols) of O; V loads are warp-broadcast
//   float4s. Softmax state in registers; corr/l passed via tiny smem arrays.
// ---------------------------------------------------------------------------
#define SQT_STRIDE 68
#define SV_STRIDE  84
#define SP_STRIDE  68

__global__ __launch_bounds__(256) void attn_kernel()
{
    extern __shared__ float sm[];
    float* sQt   = sm;                       // [80][68] transposed
    float* sKt   = sQt + 80 * SQT_STRIDE;    // [80][68] transposed
    float* sV    = sKt + 80 * SQT_STRIDE;    // [64][84]
    float* sP    = sV  + 64 * SV_STRIDE;     // [64][68]
    float* sCorr = sP  + 64 * SP_STRIDE;     // [64]
    float* sL    = sCorr + 64;               // [64]

    const int bx = blockIdx.x;
    const int qt = bx & 15;          // 16 q-tiles of 64 rows
    const int h  = (bx >> 4) & 15;
    const int c  = bx >> 8;

    const int tid = threadIdx.x;
    const int tx = tid & 15;         // score col group (4 cols)
    const int ty = tid >> 4;         // score row group (4 rows)
    const int orow = tid >> 2;       // PV row (0..63)
    const int og   = tid & 3;        // PV col group (20 cols)

    const float* qbase = g_q + (size_t)h * S_ * D_ + (size_t)(c * L_ + qt * 64) * D_;
    const float* kbase = g_k + (size_t)h * S_ * D_ + (size_t)(c * L_) * D_;
    const float* vbase = g_v + (size_t)h * S_ * D_ + (size_t)(c * L_) * D_;

    // Load Q tile transposed
    for (int i = tid; i < 64 * 80; i += 256) {
        int rr = i / 80, dd = i - rr * 80;
        sQt[dd * SQT_STRIDE + rr] = qbase[i];
    }

    float m0 = -1e30f, m1 = -1e30f, m2 = -1e30f, m3 = -1e30f;
    float l0 = 0.f, l1 = 0.f, l2 = 0.f, l3 = 0.f;
    float acc[20];
#pragma unroll
    for (int i = 0; i < 20; i++) acc[i] = 0.f;
    const float inv_scale = rsqrtf((float)D_);
    __syncthreads();

    for (int t = 0; t < 16; t++) {
        // Load K (transposed) and V tiles
        const float* kt = kbase + t * 64 * 80;
        const float* vt = vbase + t * 64 * 80;
        for (int i = tid; i < 64 * 80; i += 256) {
            int rr = i / 80, dd = i - rr * 80;
            sKt[dd * SQT_STRIDE + rr] = kt[i];
            sV [rr * SV_STRIDE + dd]  = vt[i];
        }
        __syncthreads();

        // ---- scores: 4x4 per thread ----
        float a00=0,a01=0,a02=0,a03=0, a10=0,a11=0,a12=0,a13=0;
        float a20=0,a21=0,a22=0,a23=0, a30=0,a31=0,a32=0,a33=0;
#pragma unroll 8
        for (int d = 0; d < 80; d++) {
            float4 qv = *(const float4*)(sQt + d * SQT_STRIDE + ty * 4);
            float4 kv = *(const float4*)(sKt + d * SQT_STRIDE + tx * 4);
            a00 += qv.x * kv.x; a01 += qv.x * kv.y; a02 += qv.x * kv.z; a03 += qv.x * kv.w;
            a10 += qv.y * kv.x; a11 += qv.y * kv.y; a12 += qv.y * kv.z; a13 += qv.y * kv.w;
            a20 += qv.z * kv.x; a21 += qv.z * kv.y; a22 += qv.z * kv.z; a23 += qv.z * kv.w;
            a30 += qv.w * kv.x; a31 += qv.w * kv.y; a32 += qv.w * kv.z; a33 += qv.w * kv.w;
        }

        // ---- online softmax per row (reduce over 16 tx lanes) ----
        float s00=a00*inv_scale, s01=a01*inv_scale, s02=a02*inv_scale, s03=a03*inv_scale;
        float s10=a10*inv_scale, s11=a11*inv_scale, s12=a12*inv_scale, s13=a13*inv_scale;
        float s20=a20*inv_scale, s21=a21*inv_scale, s22=a22*inv_scale, s23=a23*inv_scale;
        float s30=a30*inv_scale, s31=a31*inv_scale, s32=a32*inv_scale, s33=a33*inv_scale;

        float mx0 = fmaxf(fmaxf(s00, s01), fmaxf(s02, s03));
        float mx1 = fmaxf(fmaxf(s10, s11), fmaxf(s12, s13));
        float mx2 = fmaxf(fmaxf(s20, s21), fmaxf(s22, s23));
        float mx3 = fmaxf(fmaxf(s30, s31), fmaxf(s32, s33));
#pragma unroll
        for (int o = 1; o < 16; o <<= 1) {
            mx0 = fmaxf(mx0, __shfl_xor_sync(0xffffffffu, mx0, o));
            mx1 = fmaxf(mx1, __shfl_xor_sync(0xffffffffu, mx1, o));
            mx2 = fmaxf(mx2, __shfl_xor_sync(0xffffffffu, mx2, o));
            mx3 = fmaxf(mx3, __shfl_xor_sync(0xffffffffu, mx3, o));
        }
        float nm0 = fmaxf(m0, mx0), nm1 = fmaxf(m1, mx1);
        float nm2 = fmaxf(m2, mx2), nm3 = fmaxf(m3, mx3);

        float4 p0, p1, p2, p3;
        p0.x = __expf(s00 - nm0); p0.y = __expf(s01 - nm0); p0.z = __expf(s02 - nm0); p0.w = __expf(s03 - nm0);
        p1.x = __expf(s10 - nm1); p1.y = __expf(s11 - nm1); p1.z = __expf(s12 - nm1); p1.w = __expf(s13 - nm1);
        p2.x = __expf(s20 - nm2); p2.y = __expf(s21 - nm2); p2.z = __expf(s22 - nm2); p2.w = __expf(s23 - nm2);
        p3.x = __expf(s30 - nm3); p3.y = __expf(s31 - nm3); p3.z = __expf(s32 - nm3); p3.w = __expf(s33 - nm3);

        float su0 = p0.x + p0.y + p0.z + p0.w;
        float su1 = p1.x + p1.y + p1.z + p1.w;
        float su2 = p2.x + p2.y + p2.z + p2.w;
        float su3 = p3.x + p3.y + p3.z + p3.w;
#pragma unroll
        for (int o = 1; o < 16; o <<= 1) {
            su0 += __shfl_xor_sync(0xffffffffu, su0, o);
            su1 += __shfl_xor_sync(0xffffffffu, su1, o);
            su2 += __shfl_xor_sync(0xffffffffu, su2, o);
            su3 += __shfl_xor_sync(0xffffffffu, su3, o);
        }
        float c0 = __expf(m0 - nm0), c1 = __expf(m1 - nm1);
        float c2 = __expf(m2 - nm2), c3 = __expf(m3 - nm3);
        l0 = l0 * c0 + su0; l1 = l1 * c1 + su1;
        l2 = l2 * c2 + su2; l3 = l3 * c3 + su3;
        m0 = nm0; m1 = nm1; m2 = nm2; m3 = nm3;

        *(float4*)(sP + (ty * 4 + 0) * SP_STRIDE + tx * 4) = p0;
        *(float4*)(sP + (ty * 4 + 1) * SP_STRIDE + tx * 4) = p1;
        *(float4*)(sP + (ty * 4 + 2) * SP_STRIDE + tx * 4) = p2;
        *(float4*)(sP + (ty * 4 + 3) * SP_STRIDE + tx * 4) = p3;
        if (tx == 0) {
            sCorr[ty * 4 + 0] = c0; sCorr[ty * 4 + 1] = c1;
            sCorr[ty * 4 + 2] = c2; sCorr[ty * 4 + 3] = c3;
            sL[ty * 4 + 0] = l0; sL[ty * 4 + 1] = l1;
            sL[ty * 4 + 2] = l2; sL[ty * 4 + 3] = l3;
        }
        __syncthreads();

        // ---- PV: 1 row x 20 cols per thread ----
        float corr = sCorr[orow];
#pragma unroll
        for (int i = 0; i < 20; i++) acc[i] *= corr;

        const float* prow = sP + orow * SP_STRIDE;
#pragma unroll 4
        for (int jj = 0; jj < 64; jj++) {
            float p = prow[jj];
            const float* vp = sV + jj * SV_STRIDE + og * 20;
            float4 v0 = *(const float4*)(vp + 0);
            float4 v1 = *(const float4*)(vp + 4);
            float4 v2 = *(const float4*)(vp + 8);
            float4 v3 = *(const float4*)(vp + 12);
            float4 v4 = *(const float4*)(vp + 16);
            acc[0]  += p * v0.x; acc[1]  += p * v0.y; acc[2]  += p * v0.z; acc[3]  += p * v0.w;
            acc[4]  += p * v1.x; acc[5]  += p * v1.y; acc[6]  += p * v1.z; acc[7]  += p * v1.w;
            acc[8]  += p * v2.x; acc[9]  += p * v2.y; acc[10] += p * v2.z; acc[11] += p * v2.w;
            acc[12] += p * v3.x; acc[13] += p * v3.y; acc[14] += p * v3.z; acc[15] += p * v3.w;
            acc[16] += p * v4.x; acc[17] += p * v4.y; acc[18] += p * v4.z; acc[19] += p * v4.w;
        }
        __syncthreads();   // before next tile load overwrites sKt/sV (and sP)
    }

    float invl = 1.f / sL[orow];
    int srow = c * L_ + qt * 64 + orow;
    float* outp = g_attn + (size_t)srow * HID_ + h * D_ + og * 20;
#pragma unroll
    for (int i = 0; i < 20; i += 4) {
        float4 o;
        o.x = acc[i + 0] * invl; o.y = acc[i + 1] * invl;
        o.z = acc[i + 2] * invl; o.w = acc[i + 3] * invl;
        *(float4*)(outp + i) = o;
    }
}

#define ATTN_SMEM_BYTES ((80 * SQT_STRIDE * 2 + 64 * SV_STRIDE + 64 * SP_STRIDE + 128) * 4)

// ---------------------------------------------------------------------------
// Launch: qkv gemm -> rope/split -> attention -> proj gemm
// ---------------------------------------------------------------------------
extern "C" void kernel_launch(void* const* d_in, const int* in_sizes, int n_in,
                              void* d_out, int out_size)
{
    const float* x     = (const float*)d_in[0];
    const float* cosp  = (const float*)d_in[1];
    const float* sinp  = (const float*)d_in[2];
    const float* Wqkv  = (const float*)d_in[3];
    const float* bqkv  = (const float*)d_in[4];
    const float* Wproj = (const float*)d_in[5];
    const float* bproj = (const float*)d_in[6];
    float* out = (float*)d_out;

    float *qkv_p, *attn_p;
    cudaGetSymbolAddress((void**)&qkv_p, g_qkv);
    cudaGetSymbolAddress((void**)&attn_p, g_attn);

    static int attn_attr_set = 0;
    if (!attn_attr_set) {
        cudaFuncSetAttribute(attn_kernel,
                             cudaFuncAttributeMaxDynamicSharedMemorySize,
                             ATTN_SMEM_BYTES);
        attn_attr_set = 1;
    }

    dim3 g1(THREE_HID / 128, S_ / 128);
    sgemm_bias<<<g1, 256>>>(x, Wqkv, bqkv, qkv_p, S_, THREE_HID, HID_);

    rope_split<<<(S_ * HID_ + 255) / 256, 256>>>(cosp, sinp);

    attn_kernel<<<C_ * H_ * (L_ / 64), 256, ATTN_SMEM_BYTES>>>();

    dim3 g2(HID_ / 128, S_ / 128);
    sgemm_bias<<<g2, 256>>>(attn_p, Wproj, bproj, out, S_, HID_, HID_);
}

// round 3
// speedup vs baseline: 1.3441x; 1.1331x over previous
#include <cuda_runtime.h>
#include <math.h>

#define S_        8192
#define HID_      1280
#define H_        16
#define D_        80
#define C_        8
#define L_        1024
#define THREE_HID 3840

// Scratch (allocation-free rule: __device__ globals)
__device__ float g_qkv[(size_t)S_ * THREE_HID];   // 126 MB
__device__ float g_q[(size_t)H_ * S_ * D_];       // 40 MB, [H][S][D]
__device__ float g_k[(size_t)H_ * S_ * D_];
__device__ float g_v[(size_t)H_ * S_ * D_];
__device__ float g_attn[(size_t)S_ * HID_];       // 40 MB, [S][HID]

// ---------------------------------------------------------------------------
// Classic fp32 SGEMM: C[M,N] = A[M,K] @ B[K,N] + bias[N]
// ---------------------------------------------------------------------------
__global__ __launch_bounds__(256) void sgemm_bias(
    const float* __restrict__ A, const float* __restrict__ B,
    const float* __restrict__ bias, float* __restrict__ Cm,
    int M, int N, int K)
{
    __shared__ float As[8][128];
    __shared__ float Bs[8][128];

    const int tid = threadIdx.x;
    const int bx = blockIdx.x, by = blockIdx.y;

    const int aRow = tid >> 1;
    const int aCol = (tid & 1) * 4;
    const int bRow = tid >> 5;
    const int bCol = (tid & 31) * 4;
    const int tx = tid & 15, ty = tid >> 4;

    float acc[8][8];
#pragma unroll
    for (int i = 0; i < 8; i++)
#pragma unroll
        for (int j = 0; j < 8; j++) acc[i][j] = 0.f;

    const float* Aptr = A + (size_t)(by * 128 + aRow) * K + aCol;
    const float* Bptr = B + (size_t)bRow * N + bx * 128 + bCol;

    for (int k0 = 0; k0 < K; k0 += 8) {
        float4 av = *(const float4*)(Aptr + k0);
        As[aCol + 0][aRow] = av.x;
        As[aCol + 1][aRow] = av.y;
        As[aCol + 2][aRow] = av.z;
        As[aCol + 3][aRow] = av.w;
        *(float4*)&Bs[bRow][bCol] = *(const float4*)(Bptr + (size_t)k0 * N);
        __syncthreads();

#pragma unroll
        for (int kk = 0; kk < 8; kk++) {
            float4 a0 = *(const float4*)&As[kk][ty * 8];
            float4 a1 = *(const float4*)&As[kk][ty * 8 + 4];
            float4 b0 = *(const float4*)&Bs[kk][tx * 8];
            float4 b1 = *(const float4*)&Bs[kk][tx * 8 + 4];
            float ra[8] = {a0.x, a0.y, a0.z, a0.w, a1.x, a1.y, a1.z, a1.w};
            float rb[8] = {b0.x, b0.y, b0.z, b0.w, b1.x, b1.y, b1.z, b1.w};
#pragma unroll
            for (int i = 0; i < 8; i++)
#pragma unroll
                for (int j = 0; j < 8; j++)
                    acc[i][j] += ra[i] * rb[j];
        }
        __syncthreads();
    }

#pragma unroll
    for (int i = 0; i < 8; i++) {
        int row = by * 128 + ty * 8 + i;
#pragma unroll
        for (int j = 0; j < 8; j += 4) {
            int col = bx * 128 + tx * 8 + j;
            float4 o;
            o.x = acc[i][j + 0] + bias[col + 0];
            o.y = acc[i][j + 1] + bias[col + 1];
            o.z = acc[i][j + 2] + bias[col + 2];
            o.w = acc[i][j + 3] + bias[col + 3];
            *(float4*)(Cm + (size_t)row * N + col) = o;
        }
    }
}

// ---------------------------------------------------------------------------
// RoPE + split qkv[S,3*HID] -> q,k (rotated), v in [H][S][D] layout
// ---------------------------------------------------------------------------
__global__ void rope_split(const float* __restrict__ cosp,
                           const float* __restrict__ sinp)
{
    int idx = blockIdx.x * blockDim.x + threadIdx.x;
    if (idx >= S_ * HID_) return;
    int s   = idx / HID_;
    int col = idx - s * HID_;
    int h   = col / D_;
    int d   = col - h * D_;

    const float* base = g_qkv + (size_t)s * THREE_HID;
    float qv = base[col];
    float kv = base[HID_ + col];
    float vv = base[2 * HID_ + col];

    float c  = cosp[s * D_ + d];
    float sn = sinp[s * D_ + d];

    int off = (d < 40) ? (col + 40) : (col - 40);
    float sgn = (d < 40) ? -1.f : 1.f;
    float qrot = sgn * base[off];
    float krot = sgn * base[HID_ + off];

    size_t o = (size_t)h * S_ * D_ + (size_t)s * D_ + d;
    g_q[o] = qv * c + qrot * sn;
    g_k[o] = kv * c + krot * sn;
    g_v[o] = vv;
}

// ---------------------------------------------------------------------------
// Flash attention, 128q x 64k tiles, 256 threads.
// Score phase: thread (ty,tx) owns 8 rows (ty*8..) x 4 cols (tx*4..):
//   per d: 3x LDS.128 feed 32 FFMA  (96 B/cyc/SM << 128 crossbar limit)
// PV phase: same row group, 5 cols (tx*5..): P read as float4 over jj.
// Softmax state (m,l,corr) lives in registers (row groups match).
// ---------------------------------------------------------------------------
#define SQT_STRIDE 132   // 128 + 4 pad
#define SKT_STRIDE 68    // 64 + 4 pad
#define SV_STRIDE  84    // 80 + 4 pad
#define SP_STRIDE  68    // 64 + 4 pad

__global__ __launch_bounds__(256) void attn_kernel()
{
    extern __shared__ float sm[];
    float* sQt = sm;                        // [80][132] transposed Q
    float* sKt = sQt + 80 * SQT_STRIDE;     // [80][68]  transposed K
    float* sV  = sKt + 80 * SKT_STRIDE;     // [64][84]  row-major V
    float* sP  = sV  + 64 * SV_STRIDE;      // [128][68] row-major P

    const int bx = blockIdx.x;
    const int qt = bx & 7;            // 8 q-tiles of 128 rows
    const int h  = (bx >> 3) & 15;
    const int c  = bx >> 7;

    const int tid = threadIdx.x;
    const int tx = tid & 15;          // col group
    const int ty = tid >> 4;          // row group (8 rows)

    const float* qbase = g_q + (size_t)h * S_ * D_ + (size_t)(c * L_ + qt * 128) * D_;
    const float* kbase = g_k + (size_t)h * S_ * D_ + (size_t)(c * L_) * D_;
    const float* vbase = g_v + (size_t)h * S_ * D_ + (size_t)(c * L_) * D_;

    // Load Q tile transposed (one-time)
    for (int i = tid; i < 128 * 80; i += 256) {
        int rr = i / 80, dd = i - rr * 80;
        sQt[dd * SQT_STRIDE + rr] = qbase[i];
    }

    float m[8], l[8], acc[8][5];
#pragma unroll
    for (int i = 0; i < 8; i++) {
        m[i] = -1e30f; l[i] = 0.f;
#pragma unroll
        for (int j = 0; j < 5; j++) acc[i][j] = 0.f;
    }
    const float inv_scale = rsqrtf((float)D_);
    __syncthreads();

    for (int t = 0; t < 16; t++) {
        const float* kt = kbase + t * 64 * 80;
        const float* vt = vbase + t * 64 * 80;
        for (int i = tid; i < 64 * 80; i += 256) {
            int rr = i / 80, dd = i - rr * 80;
            sKt[dd * SKT_STRIDE + rr] = kt[i];
            sV [rr * SV_STRIDE + dd]  = vt[i];
        }
        __syncthreads();

        // ---- scores: 8x4 per thread ----
        float s[8][4];
#pragma unroll
        for (int i = 0; i < 8; i++)
#pragma unroll
            for (int j = 0; j < 4; j++) s[i][j] = 0.f;

#pragma unroll 4
        for (int d = 0; d < 80; d++) {
            float4 q0 = *(const float4*)(sQt + d * SQT_STRIDE + ty * 8);
            float4 q1 = *(const float4*)(sQt + d * SQT_STRIDE + ty * 8 + 4);
            float4 kv = *(const float4*)(sKt + d * SKT_STRIDE + tx * 4);
            float qr[8] = {q0.x, q0.y, q0.z, q0.w, q1.x, q1.y, q1.z, q1.w};
            float kr[4] = {kv.x, kv.y, kv.z, kv.w};
#pragma unroll
            for (int i = 0; i < 8; i++)
#pragma unroll
                for (int j = 0; j < 4; j++)
                    s[i][j] += qr[i] * kr[j];
        }

        // ---- online softmax (reduce over the 16 tx lanes; xor 1,2,4,8 stays
        //      within the same ty half of the warp) ----
        float corr[8];
#pragma unroll
        for (int i = 0; i < 8; i++) {
            float s0 = s[i][0] * inv_scale;
            float s1 = s[i][1] * inv_scale;
            float s2 = s[i][2] * inv_scale;
            float s3 = s[i][3] * inv_scale;
            float mx = fmaxf(fmaxf(s0, s1), fmaxf(s2, s3));
#pragma unroll
            for (int o = 1; o < 16; o <<= 1)
                mx = fmaxf(mx, __shfl_xor_sync(0xffffffffu, mx, o));
            float nm = fmaxf(m[i], mx);
            float4 p;
            p.x = __expf(s0 - nm); p.y = __expf(s1 - nm);
            p.z = __expf(s2 - nm); p.w = __expf(s3 - nm);
            float su = p.x + p.y + p.z + p.w;
#pragma unroll
            for (int o = 1; o < 16; o <<= 1)
                su += __shfl_xor_sync(0xffffffffu, su, o);
            corr[i] = __expf(m[i] - nm);
            l[i] = l[i] * corr[i] + su;
            m[i] = nm;
            *(float4*)(sP + (ty * 8 + i) * SP_STRIDE + tx * 4) = p;
        }
        __syncthreads();

        // ---- PV: 8 rows x 5 cols per thread; P as float4 over jj ----
#pragma unroll
        for (int i = 0; i < 8; i++) {
            float cr = corr[i];
#pragma unroll
            for (int j = 0; j < 5; j++) acc[i][j] *= cr;
        }

        const float* prow = sP + (ty * 8) * SP_STRIDE;
#pragma unroll 2
        for (int j0 = 0; j0 < 64; j0 += 4) {
            float4 p4[8];
#pragma unroll
            for (int i = 0; i < 8; i++)
                p4[i] = *(const float4*)(prow + i * SP_STRIDE + j0);
#pragma unroll
            for (int jj = 0; jj < 4; jj++) {
                const float* vp = sV + (j0 + jj) * SV_STRIDE + tx * 5;
                float v0 = vp[0], v1 = vp[1], v2 = vp[2], v3 = vp[3], v4 = vp[4];
#pragma unroll
                for (int i = 0; i < 8; i++) {
                    float p = (jj == 0) ? p4[i].x : (jj == 1) ? p4[i].y
                             : (jj == 2) ? p4[i].z : p4[i].w;
                    acc[i][0] += p * v0;
                    acc[i][1] += p * v1;
                    acc[i][2] += p * v2;
                    acc[i][3] += p * v3;
                    acc[i][4] += p * v4;
                }
            }
        }
        __syncthreads();   // before next tile overwrites sKt/sV/sP
    }

    // ---- epilogue ----
#pragma unroll
    for (int i = 0; i < 8; i++) {
        float invl = 1.f / l[i];
        int srow = c * L_ + qt * 128 + ty * 8 + i;
        float* outp = g_attn + (size_t)srow * HID_ + h * D_ + tx * 5;
#pragma unroll
        for (int j = 0; j < 5; j++)
            outp[j] = acc[i][j] * invl;
    }
}

#define ATTN_SMEM_BYTES ((80 * SQT_STRIDE + 80 * SKT_STRIDE + 64 * SV_STRIDE + 128 * SP_STRIDE) * 4)

// ---------------------------------------------------------------------------
// Launch: qkv gemm -> rope/split -> attention -> proj gemm
// ---------------------------------------------------------------------------
extern "C" void kernel_launch(void* const* d_in, const int* in_sizes, int n_in,
                              void* d_out, int out_size)
{
    const float* x     = (const float*)d_in[0];
    const float* cosp  = (const float*)d_in[1];
    const float* sinp  = (const float*)d_in[2];
    const float* Wqkv  = (const float*)d_in[3];
    const float* bqkv  = (const float*)d_in[4];
    const float* Wproj = (const float*)d_in[5];
    const float* bproj = (const float*)d_in[6];
    float* out = (float*)d_out;

    float *qkv_p, *attn_p;
    cudaGetSymbolAddress((void**)&qkv_p, g_qkv);
    cudaGetSymbolAddress((void**)&attn_p, g_attn);

    static int attn_attr_set = 0;
    if (!attn_attr_set) {
        cudaFuncSetAttribute(attn_kernel,
                             cudaFuncAttributeMaxDynamicSharedMemorySize,
                             ATTN_SMEM_BYTES);
        attn_attr_set = 1;
    }

    dim3 g1(THREE_HID / 128, S_ / 128);
    sgemm_bias<<<g1, 256>>>(x, Wqkv, bqkv, qkv_p, S_, THREE_HID, HID_);

    rope_split<<<(S_ * HID_ + 255) / 256, 256>>>(cosp, sinp);

    attn_kernel<<<C_ * H_ * (L_ / 128), 256, ATTN_SMEM_BYTES>>>();

    dim3 g2(HID_ / 128, S_ / 128);
    sgemm_bias<<<g2, 256>>>(attn_p, Wproj, bproj, out, S_, HID_, HID_);
}

// round 5
// speedup vs baseline: 2.0352x; 1.5142x over previous
#include <cuda_runtime.h>
#include <cuda_bf16.h>
#include <cstdint>
#include <math.h>

#define S_        8192
#define HID_      1280
#define H_        16
#define D_        80
#define C_        8
#define L_        1024
#define THREE_HID 3840

// ---------------------------------------------------------------------------
// Scratch (allocation-free rule: __device__ globals)
// ---------------------------------------------------------------------------
__device__ float g_qkv[(size_t)S_ * THREE_HID];
__device__ float g_q[(size_t)H_ * S_ * D_];
__device__ float g_k[(size_t)H_ * S_ * D_];
__device__ float g_v[(size_t)H_ * S_ * D_];
__device__ __nv_bfloat16 g_xhi[(size_t)S_ * HID_];
__device__ __nv_bfloat16 g_xlo[(size_t)S_ * HID_];
__device__ __nv_bfloat16 g_wqt_hi[(size_t)THREE_HID * HID_];  // Wqkv^T [N][K]
__device__ __nv_bfloat16 g_wqt_lo[(size_t)THREE_HID * HID_];
__device__ __nv_bfloat16 g_wpt_hi[(size_t)HID_ * HID_];       // Wproj^T [N][K]
__device__ __nv_bfloat16 g_wpt_lo[(size_t)HID_ * HID_];
__device__ __nv_bfloat16 g_ahi[(size_t)S_ * HID_];            // attn out hi/lo
__device__ __nv_bfloat16 g_alo[(size_t)S_ * HID_];

__device__ __forceinline__ uint32_t smem_u32(const void* p) {
    uint32_t a;
    asm("{ .reg .u64 t; cvta.to.shared.u64 t, %1; cvt.u32.u64 %0, t; }"
        : "=r"(a) : "l"(p));
    return a;
}

// ---------------------------------------------------------------------------
// bf16-split conversion kernels
// ---------------------------------------------------------------------------
__global__ void split_rows(const float* __restrict__ in,
                           __nv_bfloat16* __restrict__ hi,
                           __nv_bfloat16* __restrict__ lo, int n)
{
    int i = blockIdx.x * blockDim.x + threadIdx.x;
    if (i >= n) return;
    float v = in[i];
    __nv_bfloat16 h = __float2bfloat16(v);
    hi[i] = h;
    lo[i] = __float2bfloat16(v - __bfloat162float(h));
}

// W[K][N] row-major -> out[N][K] hi/lo (transpose + split)
__global__ void split_t(const float* __restrict__ W,
                        __nv_bfloat16* __restrict__ hi,
                        __nv_bfloat16* __restrict__ lo, int K, int N)
{
    __shared__ float t[32][33];
    int n0 = blockIdx.x * 32, k0 = blockIdx.y * 32;
    int tx = threadIdx.x, ty = threadIdx.y;   // (32, 8)
#pragma unroll
    for (int i = 0; i < 32; i += 8)
        t[ty + i][tx] = W[(size_t)(k0 + ty + i) * N + n0 + tx];
    __syncthreads();
#pragma unroll
    for (int i = 0; i < 32; i += 8) {
        float v = t[tx][ty + i];
        __nv_bfloat16 h = __float2bfloat16(v);
        size_t o = (size_t)(n0 + ty + i) * K + k0 + tx;
        hi[o] = h;
        lo[o] = __float2bfloat16(v - __bfloat162float(h));
    }
}

// ---------------------------------------------------------------------------
// bf16-split GEMM via mma.sync (HMMA): C[M,N] = A @ B^T + bias
// A hi/lo [M][K], B hi/lo [N][K].  128x128 CTA tile, BK=32, 8 warps,
// warp tile 32(M) x 64(N).  cp.async double-buffered smem.
// 3-term split: Ah*Bh + Ah*Bl + Al*Bh  (fp32 accumulate).
// ---------------------------------------------------------------------------
#define AST 40                       // smem row stride (bf16 elems), 80 bytes
#define MAT_ELEMS (128 * AST)        // 5120 elems = 10240 bytes per matrix
#define GEMM_SMEM_BYTES (2 * 4 * MAT_ELEMS * 2)   // 81920

__global__ __launch_bounds__(256) void mma_gemm_bias(
    const __nv_bfloat16* __restrict__ Ahi, const __nv_bfloat16* __restrict__ Alo,
    const __nv_bfloat16* __restrict__ Bhi, const __nv_bfloat16* __restrict__ Blo,
    const float* __restrict__ bias, float* __restrict__ Cm,
    int M, int N, int K)
{
    extern __shared__ __nv_bfloat16 smb[];
    const uint32_t sb = smem_u32(smb);

    const int tid  = threadIdx.x;
    const int lane = tid & 31, warp = tid >> 5;
    const int warpM = warp & 3;       // rows warpM*32
    const int warpN = warp >> 2;      // cols warpN*64
    const int quad = lane >> 3, l8 = lane & 7;
    const int tileN = blockIdx.x, tileM = blockIdx.y;

    const __nv_bfloat16* gAh = Ahi + (size_t)(tileM * 128) * K;
    const __nv_bfloat16* gAl = Alo + (size_t)(tileM * 128) * K;
    const __nv_bfloat16* gBh = Bhi + (size_t)(tileN * 128) * K;
    const __nv_bfloat16* gBl = Blo + (size_t)(tileN * 128) * K;

    float c[2][8][4];
#pragma unroll
    for (int mi = 0; mi < 2; mi++)
#pragma unroll
        for (int nt = 0; nt < 8; nt++)
#pragma unroll
            for (int r = 0; r < 4; r++) c[mi][nt][r] = 0.f;

    const int nch = K >> 5;   // K/32

    // ---- cp.async issue for one chunk into buffer `buf` ----
    auto issue = [&](int ch, int buf) {
        const int k0 = ch * 32;
#pragma unroll
        for (int p = 0; p < 2; p++) {
            int idx = tid + p * 256;          // 0..511
            int row = idx >> 2, seg = idx & 3;
            uint32_t so = (uint32_t)((row * AST + seg * 8) * 2);
            size_t go = (size_t)row * K + k0 + seg * 8;
            uint32_t s0 = sb + (uint32_t)(buf * 4 * MAT_ELEMS * 2) + so;
            asm volatile("cp.async.cg.shared.global [%0], [%1], 16;"
                         :: "r"(s0), "l"(gAh + go));
            asm volatile("cp.async.cg.shared.global [%0], [%1], 16;"
                         :: "r"(s0 + 1 * MAT_ELEMS * 2), "l"(gAl + go));
            asm volatile("cp.async.cg.shared.global [%0], [%1], 16;"
                         :: "r"(s0 + 2 * MAT_ELEMS * 2), "l"(gBh + go));
            asm volatile("cp.async.cg.shared.global [%0], [%1], 16;"
                         :: "r"(s0 + 3 * MAT_ELEMS * 2), "l"(gBl + go));
        }
        asm volatile("cp.async.commit_group;" ::: "memory");
    };

    issue(0, 0);

    for (int ch = 0; ch < nch; ch++) {
        if (ch + 1 < nch) {
            issue(ch + 1, (ch + 1) & 1);
            asm volatile("cp.async.wait_group 1;" ::: "memory");
        } else {
            asm volatile("cp.async.wait_group 0;" ::: "memory");
        }
        __syncthreads();

        const uint32_t base = sb + (uint32_t)((ch & 1) * 4 * MAT_ELEMS * 2);
        const uint32_t aHb = base;
        const uint32_t aLb = base + 1 * MAT_ELEMS * 2;
        const uint32_t bHb = base + 2 * MAT_ELEMS * 2;
        const uint32_t bLb = base + 3 * MAT_ELEMS * 2;

#pragma unroll
        for (int s = 0; s < 2; s++) {
            uint32_t ah[2][4], al[2][4], bh[4][4], bl[4][4];

            // A fragments: 2 m16 tiles, hi & lo
#pragma unroll
            for (int mi = 0; mi < 2; mi++) {
                int row = warpM * 32 + mi * 16 + (quad & 1) * 8 + l8;
                int ke  = s * 16 + (quad >> 1) * 8;
                uint32_t ad = aHb + (uint32_t)((row * AST + ke) * 2);
                asm volatile("ldmatrix.sync.aligned.m8n8.x4.shared.b16 {%0,%1,%2,%3}, [%4];"
                             : "=r"(ah[mi][0]), "=r"(ah[mi][1]), "=r"(ah[mi][2]), "=r"(ah[mi][3])
                             : "r"(ad));
                ad = aLb + (uint32_t)((row * AST + ke) * 2);
                asm volatile("ldmatrix.sync.aligned.m8n8.x4.shared.b16 {%0,%1,%2,%3}, [%4];"
                             : "=r"(al[mi][0]), "=r"(al[mi][1]), "=r"(al[mi][2]), "=r"(al[mi][3])
                             : "r"(ad));
            }
            // B fragments: 4 ldmatrix.x4 cover n16 each (two n8 tiles), hi & lo
#pragma unroll
            for (int nj = 0; nj < 4; nj++) {
                int nrow = warpN * 64 + nj * 16 + (quad >> 1) * 8 + l8;
                int ke   = s * 16 + (quad & 1) * 8;
                uint32_t bd = bHb + (uint32_t)((nrow * AST + ke) * 2);
                asm volatile("ldmatrix.sync.aligned.m8n8.x4.shared.b16 {%0,%1,%2,%3}, [%4];"
                             : "=r"(bh[nj][0]), "=r"(bh[nj][1]), "=r"(bh[nj][2]), "=r"(bh[nj][3])
                             : "r"(bd));
                bd = bLb + (uint32_t)((nrow * AST + ke) * 2);
                asm volatile("ldmatrix.sync.aligned.m8n8.x4.shared.b16 {%0,%1,%2,%3}, [%4];"
                             : "=r"(bl[nj][0]), "=r"(bl[nj][1]), "=r"(bl[nj][2]), "=r"(bl[nj][3])
                             : "r"(bd));
            }

#define MMA(cc, aa, b0, b1)                                                     \
    asm volatile("mma.sync.aligned.m16n8k16.row.col.f32.bf16.bf16.f32 "         \
                 "{%0,%1,%2,%3},{%4,%5,%6,%7},{%8,%9},{%0,%1,%2,%3};"           \
                 : "+f"((cc)[0]), "+f"((cc)[1]), "+f"((cc)[2]), "+f"((cc)[3])   \
                 : "r"((aa)[0]), "r"((aa)[1]), "r"((aa)[2]), "r"((aa)[3]),      \
                   "r"(b0), "r"(b1))

#pragma unroll
            for (int mi = 0; mi < 2; mi++) {
#pragma unroll
                for (int nt = 0; nt < 8; nt++) {
                    int nj = nt >> 1, hh = (nt & 1) * 2;
                    MMA(c[mi][nt], ah[mi], bh[nj][hh], bh[nj][hh + 1]);
                    MMA(c[mi][nt], ah[mi], bl[nj][hh], bl[nj][hh + 1]);
                    MMA(c[mi][nt], al[mi], bh[nj][hh], bh[nj][hh + 1]);
                }
            }
#undef MMA
        }
        __syncthreads();
    }

    // ---- epilogue: add bias, store fp32 ----
    const int m0 = tileM * 128 + warpM * 32;
    const int n0 = tileN * 128 + warpN * 64;
    const int rq = lane >> 2, cq = (lane & 3) * 2;
#pragma unroll
    for (int mi = 0; mi < 2; mi++) {
#pragma unroll
        for (int nt = 0; nt < 8; nt++) {
            int col = n0 + nt * 8 + cq;
            float2 b2 = *(const float2*)(bias + col);
            int r0 = m0 + mi * 16 + rq;
            float2 o0, o1;
            o0.x = c[mi][nt][0] + b2.x; o0.y = c[mi][nt][1] + b2.y;
            o1.x = c[mi][nt][2] + b2.x; o1.y = c[mi][nt][3] + b2.y;
            *(float2*)(Cm + (size_t)r0 * N + col)       = o0;
            *(float2*)(Cm + (size_t)(r0 + 8) * N + col) = o1;
        }
    }
}

// ---------------------------------------------------------------------------
// RoPE + split qkv[S,3*HID] -> q,k (rotated), v in [H][S][D] layout
// ---------------------------------------------------------------------------
__global__ void rope_split(const float* __restrict__ cosp,
                           const float* __restrict__ sinp)
{
    int idx = blockIdx.x * blockDim.x + threadIdx.x;
    if (idx >= S_ * HID_) return;
    int s   = idx / HID_;
    int col = idx - s * HID_;
    int h   = col / D_;
    int d   = col - h * D_;

    const float* base = g_qkv + (size_t)s * THREE_HID;
    float qv = base[col];
    float kv = base[HID_ + col];
    float vv = base[2 * HID_ + col];

    float c  = cosp[s * D_ + d];
    float sn = sinp[s * D_ + d];

    int off = (d < 40) ? (col + 40) : (col - 40);
    float sgn = (d < 40) ? -1.f : 1.f;
    float qrot = sgn * base[off];
    float krot = sgn * base[HID_ + off];

    size_t o = (size_t)h * S_ * D_ + (size_t)s * D_ + d;
    g_q[o] = qv * c + qrot * sn;
    g_k[o] = kv * c + krot * sn;
    g_v[o] = vv;
}

// ---------------------------------------------------------------------------
// Flash attention, 128q x 64k tiles, 256 threads.  Epilogue emits bf16 hi/lo
// directly for the proj GEMM.
// ---------------------------------------------------------------------------
#define SQT_STRIDE 132
#define SKT_STRIDE 68
#define SV_STRIDE  84
#define SP_STRIDE  68

__global__ __launch_bounds__(256) void attn_kernel()
{
    extern __shared__ float sm[];
    float* sQt = sm;
    float* sKt = sQt + 80 * SQT_STRIDE;
    float* sV  = sKt + 80 * SKT_STRIDE;
    float* sP  = sV  + 64 * SV_STRIDE;

    const int bx = blockIdx.x;
    const int qt = bx & 7;
    const int h  = (bx >> 3) & 15;
    const int c  = bx >> 7;

    const int tid = threadIdx.x;
    const int tx = tid & 15;
    const int ty = tid >> 4;

    const float* qbase = g_q + (size_t)h * S_ * D_ + (size_t)(c * L_ + qt * 128) * D_;
    const float* kbase = g_k + (size_t)h * S_ * D_ + (size_t)(c * L_) * D_;
    const float* vbase = g_v + (size_t)h * S_ * D_ + (size_t)(c * L_) * D_;

    for (int i = tid; i < 128 * 80; i += 256) {
        int rr = i / 80, dd = i - rr * 80;
        sQt[dd * SQT_STRIDE + rr] = qbase[i];
    }

    float m[8], l[8], acc[8][5];
#pragma unroll
    for (int i = 0; i < 8; i++) {
        m[i] = -1e30f; l[i] = 0.f;
#pragma unroll
        for (int j = 0; j < 5; j++) acc[i][j] = 0.f;
    }
    const float inv_scale = rsqrtf((float)D_);
    __syncthreads();

    for (int t = 0; t < 16; t++) {
        const float* kt = kbase + t * 64 * 80;
        const float* vt = vbase + t * 64 * 80;
        for (int i = tid; i < 64 * 80; i += 256) {
            int rr = i / 80, dd = i - rr * 80;
            sKt[dd * SKT_STRIDE + rr] = kt[i];
            sV [rr * SV_STRIDE + dd]  = vt[i];
        }
        __syncthreads();

        float s[8][4];
#pragma unroll
        for (int i = 0; i < 8; i++)
#pragma unroll
            for (int j = 0; j < 4; j++) s[i][j] = 0.f;

#pragma unroll 4
        for (int d = 0; d < 80; d++) {
            float4 q0 = *(const float4*)(sQt + d * SQT_STRIDE + ty * 8);
            float4 q1 = *(const float4*)(sQt + d * SQT_STRIDE + ty * 8 + 4);
            float4 kv = *(const float4*)(sKt + d * SKT_STRIDE + tx * 4);
            float qr[8] = {q0.x, q0.y, q0.z, q0.w, q1.x, q1.y, q1.z, q1.w};
            float kr[4] = {kv.x, kv.y, kv.z, kv.w};
#pragma unroll
            for (int i = 0; i < 8; i++)
#pragma unroll
                for (int j = 0; j < 4; j++)
                    s[i][j] += qr[i] * kr[j];
        }

        float corr[8];
#pragma unroll
        for (int i = 0; i < 8; i++) {
            float s0 = s[i][0] * inv_scale;
            float s1 = s[i][1] * inv_scale;
            float s2 = s[i][2] * inv_scale;
            float s3 = s[i][3] * inv_scale;
            float mx = fmaxf(fmaxf(s0, s1), fmaxf(s2, s3));
#pragma unroll
            for (int o = 1; o < 16; o <<= 1)
                mx = fmaxf(mx, __shfl_xor_sync(0xffffffffu, mx, o));
            float nm = fmaxf(m[i], mx);
            float4 p;
            p.x = __expf(s0 - nm); p.y = __expf(s1 - nm);
            p.z = __expf(s2 - nm); p.w = __expf(s3 - nm);
            float su = p.x + p.y + p.z + p.w;
#pragma unroll
            for (int o = 1; o < 16; o <<= 1)
                su += __shfl_xor_sync(0xffffffffu, su, o);
            corr[i] = __expf(m[i] - nm);
            l[i] = l[i] * corr[i] + su;
            m[i] = nm;
            *(float4*)(sP + (ty * 8 + i) * SP_STRIDE + tx * 4) = p;
        }
        __syncthreads();

#pragma unroll
        for (int i = 0; i < 8; i++) {
            float cr = corr[i];
#pragma unroll
            for (int j = 0; j < 5; j++) acc[i][j] *= cr;
        }

        const float* prow = sP + (ty * 8) * SP_STRIDE;
#pragma unroll 2
        for (int j0 = 0; j0 < 64; j0 += 4) {
            float4 p4[8];
#pragma unroll
            for (int i = 0; i < 8; i++)
                p4[i] = *(const float4*)(prow + i * SP_STRIDE + j0);
#pragma unroll
            for (int jj = 0; jj < 4; jj++) {
                const float* vp = sV + (j0 + jj) * SV_STRIDE + tx * 5;
                float v0 = vp[0], v1 = vp[1], v2 = vp[2], v3 = vp[3], v4 = vp[4];
#pragma unroll
                for (int i = 0; i < 8; i++) {
                    float p = (jj == 0) ? p4[i].x : (jj == 1) ? p4[i].y
                             : (jj == 2) ? p4[i].z : p4[i].w;
                    acc[i][0] += p * v0;
                    acc[i][1] += p * v1;
                    acc[i][2] += p * v2;
                    acc[i][3] += p * v3;
                    acc[i][4] += p * v4;
                }
            }
        }
        __syncthreads();
    }

    // epilogue: write bf16 hi/lo for the proj GEMM
#pragma unroll
    for (int i = 0; i < 8; i++) {
        float invl = 1.f / l[i];
        int srow = c * L_ + qt * 128 + ty * 8 + i;
        size_t ob = (size_t)srow * HID_ + h * D_ + tx * 5;
#pragma unroll
        for (int j = 0; j < 5; j++) {
            float v = acc[i][j] * invl;
            __nv_bfloat16 hv = __float2bfloat16(v);
            g_ahi[ob + j] = hv;
            g_alo[ob + j] = __float2bfloat16(v - __bfloat162float(hv));
        }
    }
}

#define ATTN_SMEM_BYTES ((80 * SQT_STRIDE + 80 * SKT_STRIDE + 64 * SV_STRIDE + 128 * SP_STRIDE) * 4)

// ---------------------------------------------------------------------------
// Launch pipeline
// ---------------------------------------------------------------------------
extern "C" void kernel_launch(void* const* d_in, const int* in_sizes, int n_in,
                              void* d_out, int out_size)
{
    const float* x     = (const float*)d_in[0];
    const float* cosp  = (const float*)d_in[1];
    const float* sinp  = (const float*)d_in[2];
    const float* Wqkv  = (const float*)d_in[3];
    const float* bqkv  = (const float*)d_in[4];
    const float* Wproj = (const float*)d_in[5];
    const float* bproj = (const float*)d_in[6];
    float* out = (float*)d_out;

    float *qkv_p;
    __nv_bfloat16 *xhi, *xlo, *wqh, *wql, *wph, *wpl, *ahi, *alo;
    cudaGetSymbolAddress((void**)&qkv_p, g_qkv);
    cudaGetSymbolAddress((void**)&xhi, g_xhi);
    cudaGetSymbolAddress((void**)&xlo, g_xlo);
    cudaGetSymbolAddress((void**)&wqh, g_wqt_hi);
    cudaGetSymbolAddress((void**)&wql, g_wqt_lo);
    cudaGetSymbolAddress((void**)&wph, g_wpt_hi);
    cudaGetSymbolAddress((void**)&wpl, g_wpt_lo);
    cudaGetSymbolAddress((void**)&ahi, g_ahi);
    cudaGetSymbolAddress((void**)&alo, g_alo);

    static int attr_set = 0;
    if (!attr_set) {
        cudaFuncSetAttribute(attn_kernel,
                             cudaFuncAttributeMaxDynamicSharedMemorySize,
                             ATTN_SMEM_BYTES);
        cudaFuncSetAttribute(mma_gemm_bias,
                             cudaFuncAttributeMaxDynamicSharedMemorySize,
                             GEMM_SMEM_BYTES);
        attr_set = 1;
    }

    // conversions
    split_rows<<<(S_ * HID_ + 255) / 256, 256>>>(x, xhi, xlo, S_ * HID_);
    split_t<<<dim3(THREE_HID / 32, HID_ / 32), dim3(32, 8)>>>(Wqkv, wqh, wql, HID_, THREE_HID);
    split_t<<<dim3(HID_ / 32, HID_ / 32), dim3(32, 8)>>>(Wproj, wph, wpl, HID_, HID_);

    // QKV GEMM (HMMA bf16-split)
    mma_gemm_bias<<<dim3(THREE_HID / 128, S_ / 128), 256, GEMM_SMEM_BYTES>>>(
        xhi, xlo, wqh, wql, bqkv, qkv_p, S_, THREE_HID, HID_);

    rope_split<<<(S_ * HID_ + 255) / 256, 256>>>(cosp, sinp);

    attn_kernel<<<C_ * H_ * (L_ / 128), 256, ATTN_SMEM_BYTES>>>();

    // proj GEMM (HMMA bf16-split)
    mma_gemm_bias<<<dim3(HID_ / 128, S_ / 128), 256, GEMM_SMEM_BYTES>>>(
        ahi, alo, wph, wpl, bproj, out, S_, HID_, HID_);
}

// round 6
// speedup vs baseline: 3.8283x; 1.8811x over previous
#include <cuda_runtime.h>
#include <cuda_bf16.h>
#include <cstdint>
#include <math.h>

#define S_        8192
#define HID_      1280
#define H_        16
#define D_        80
#define C_        8
#define L_        1024
#define THREE_HID 3840

// ---------------------------------------------------------------------------
// Scratch (allocation-free rule: __device__ globals)
// ---------------------------------------------------------------------------
__device__ float g_qkv[(size_t)S_ * THREE_HID];
__device__ __nv_bfloat16 g_xhi[(size_t)S_ * HID_];
__device__ __nv_bfloat16 g_xlo[(size_t)S_ * HID_];
__device__ __nv_bfloat16 g_wqt_hi[(size_t)THREE_HID * HID_];  // Wqkv^T [N][K]
__device__ __nv_bfloat16 g_wqt_lo[(size_t)THREE_HID * HID_];
__device__ __nv_bfloat16 g_wpt_hi[(size_t)HID_ * HID_];       // Wproj^T [N][K]
__device__ __nv_bfloat16 g_wpt_lo[(size_t)HID_ * HID_];
__device__ __nv_bfloat16 g_ahi[(size_t)S_ * HID_];            // attn out hi/lo
__device__ __nv_bfloat16 g_alo[(size_t)S_ * HID_];
// RoPE'd Q (pre-scaled by 1/sqrt(D)), K, V in [H][S][D], bf16 hi/lo
__device__ __nv_bfloat16 g_qhi[(size_t)H_ * S_ * D_];
__device__ __nv_bfloat16 g_qlo[(size_t)H_ * S_ * D_];
__device__ __nv_bfloat16 g_khi[(size_t)H_ * S_ * D_];
__device__ __nv_bfloat16 g_klo[(size_t)H_ * S_ * D_];
__device__ __nv_bfloat16 g_vhi[(size_t)H_ * S_ * D_];
__device__ __nv_bfloat16 g_vlo[(size_t)H_ * S_ * D_];

__device__ __forceinline__ uint32_t smem_u32(const void* p) {
    uint32_t a;
    asm("{ .reg .u64 t; cvta.to.shared.u64 t, %1; cvt.u32.u64 %0, t; }"
        : "=r"(a) : "l"(p));
    return a;
}
// pack two f32 -> bf16x2 (first arg -> low half)
__device__ __forceinline__ uint32_t pk2(float lo, float hi) {
    uint32_t r;
    asm("cvt.rn.bf16x2.f32 %0, %1, %2;" : "=r"(r) : "f"(hi), "f"(lo));
    return r;
}
__device__ __forceinline__ float lo_of(uint32_t p) { return __uint_as_float(p << 16); }
__device__ __forceinline__ float hi_of(uint32_t p) { return __uint_as_float(p & 0xffff0000u); }

#define MMA4(cc, aa, b0, b1)                                                    \
    asm volatile("mma.sync.aligned.m16n8k16.row.col.f32.bf16.bf16.f32 "         \
                 "{%0,%1,%2,%3},{%4,%5,%6,%7},{%8,%9},{%0,%1,%2,%3};"           \
                 : "+f"((cc)[0]), "+f"((cc)[1]), "+f"((cc)[2]), "+f"((cc)[3])   \
                 : "r"((aa)[0]), "r"((aa)[1]), "r"((aa)[2]), "r"((aa)[3]),      \
                   "r"(b0), "r"(b1))
#define LDSM4(r, addr)                                                          \
    asm volatile("ldmatrix.sync.aligned.m8n8.x4.shared.b16 {%0,%1,%2,%3}, [%4];"\
                 : "=r"((r)[0]), "=r"((r)[1]), "=r"((r)[2]), "=r"((r)[3])       \
                 : "r"(addr))
#define LDSM4T(r, addr)                                                         \
    asm volatile("ldmatrix.sync.aligned.m8n8.x4.trans.shared.b16 {%0,%1,%2,%3}, [%4];" \
                 : "=r"((r)[0]), "=r"((r)[1]), "=r"((r)[2]), "=r"((r)[3])       \
                 : "r"(addr))
#define CPA16(dst, src)                                                         \
    asm volatile("cp.async.cg.shared.global [%0], [%1], 16;" :: "r"(dst), "l"(src))

// ---------------------------------------------------------------------------
// bf16-split conversion kernels
// ---------------------------------------------------------------------------
__global__ void split_rows(const float* __restrict__ in,
                           __nv_bfloat16* __restrict__ hi,
                           __nv_bfloat16* __restrict__ lo, int n)
{
    int i = blockIdx.x * blockDim.x + threadIdx.x;
    if (i >= n) return;
    float v = in[i];
    __nv_bfloat16 h = __float2bfloat16(v);
    hi[i] = h;
    lo[i] = __float2bfloat16(v - __bfloat162float(h));
}

__global__ void split_t(const float* __restrict__ W,
                        __nv_bfloat16* __restrict__ hi,
                        __nv_bfloat16* __restrict__ lo, int K, int N)
{
    __shared__ float t[32][33];
    int n0 = blockIdx.x * 32, k0 = blockIdx.y * 32;
    int tx = threadIdx.x, ty = threadIdx.y;   // (32, 8)
#pragma unroll
    for (int i = 0; i < 32; i += 8)
        t[ty + i][tx] = W[(size_t)(k0 + ty + i) * N + n0 + tx];
    __syncthreads();
#pragma unroll
    for (int i = 0; i < 32; i += 8) {
        float v = t[tx][ty + i];
        __nv_bfloat16 h = __float2bfloat16(v);
        size_t o = (size_t)(n0 + ty + i) * K + k0 + tx;
        hi[o] = h;
        lo[o] = __float2bfloat16(v - __bfloat162float(h));
    }
}

// ---------------------------------------------------------------------------
// bf16-split GEMM via mma.sync: C = A @ B^T + bias.  128x128 tile, BK=32,
// 8 warps (32x64 each), cp.async double buffer, 3-term split.
// ---------------------------------------------------------------------------
#define AST 40
#define MAT_ELEMS (128 * AST)
#define GEMM_SMEM_BYTES (2 * 4 * MAT_ELEMS * 2)   // 81920

__global__ __launch_bounds__(256, 2) void mma_gemm_bias(
    const __nv_bfloat16* __restrict__ Ahi, const __nv_bfloat16* __restrict__ Alo,
    const __nv_bfloat16* __restrict__ Bhi, const __nv_bfloat16* __restrict__ Blo,
    const float* __restrict__ bias, float* __restrict__ Cm,
    int M, int N, int K)
{
    extern __shared__ __nv_bfloat16 smb[];
    const uint32_t sb = smem_u32(smb);

    const int tid  = threadIdx.x;
    const int lane = tid & 31, warp = tid >> 5;
    const int warpM = warp & 3;
    const int warpN = warp >> 2;
    const int quad = lane >> 3, l8 = lane & 7;
    const int tileN = blockIdx.x, tileM = blockIdx.y;

    const __nv_bfloat16* gAh = Ahi + (size_t)(tileM * 128) * K;
    const __nv_bfloat16* gAl = Alo + (size_t)(tileM * 128) * K;
    const __nv_bfloat16* gBh = Bhi + (size_t)(tileN * 128) * K;
    const __nv_bfloat16* gBl = Blo + (size_t)(tileN * 128) * K;

    float c[2][8][4];
#pragma unroll
    for (int mi = 0; mi < 2; mi++)
#pragma unroll
        for (int nt = 0; nt < 8; nt++)
#pragma unroll
            for (int r = 0; r < 4; r++) c[mi][nt][r] = 0.f;

    const int nch = K >> 5;

    auto issue = [&](int ch, int buf) {
        const int k0 = ch * 32;
#pragma unroll
        for (int p = 0; p < 2; p++) {
            int idx = tid + p * 256;
            int row = idx >> 2, seg = idx & 3;
            uint32_t so = (uint32_t)((row * AST + seg * 8) * 2);
            size_t go = (size_t)row * K + k0 + seg * 8;
            uint32_t s0 = sb + (uint32_t)(buf * 4 * MAT_ELEMS * 2) + so;
            CPA16(s0,                     gAh + go);
            CPA16(s0 + 1 * MAT_ELEMS * 2, gAl + go);
            CPA16(s0 + 2 * MAT_ELEMS * 2, gBh + go);
            CPA16(s0 + 3 * MAT_ELEMS * 2, gBl + go);
        }
        asm volatile("cp.async.commit_group;" ::: "memory");
    };

    issue(0, 0);

    for (int ch = 0; ch < nch; ch++) {
        if (ch + 1 < nch) {
            issue(ch + 1, (ch + 1) & 1);
            asm volatile("cp.async.wait_group 1;" ::: "memory");
        } else {
            asm volatile("cp.async.wait_group 0;" ::: "memory");
        }
        __syncthreads();

        const uint32_t base = sb + (uint32_t)((ch & 1) * 4 * MAT_ELEMS * 2);
        const uint32_t aHb = base;
        const uint32_t aLb = base + 1 * MAT_ELEMS * 2;
        const uint32_t bHb = base + 2 * MAT_ELEMS * 2;
        const uint32_t bLb = base + 3 * MAT_ELEMS * 2;

#pragma unroll
        for (int s = 0; s < 2; s++) {
            uint32_t ah[2][4], al[2][4], bh[4][4], bl[4][4];
#pragma unroll
            for (int mi = 0; mi < 2; mi++) {
                int row = warpM * 32 + mi * 16 + (quad & 1) * 8 + l8;
                int ke  = s * 16 + (quad >> 1) * 8;
                LDSM4(ah[mi], aHb + (uint32_t)((row * AST + ke) * 2));
                LDSM4(al[mi], aLb + (uint32_t)((row * AST + ke) * 2));
            }
#pragma unroll
            for (int nj = 0; nj < 4; nj++) {
                int nrow = warpN * 64 + nj * 16 + (quad >> 1) * 8 + l8;
                int ke   = s * 16 + (quad & 1) * 8;
                LDSM4(bh[nj], bHb + (uint32_t)((nrow * AST + ke) * 2));
                LDSM4(bl[nj], bLb + (uint32_t)((nrow * AST + ke) * 2));
            }
#pragma unroll
            for (int mi = 0; mi < 2; mi++) {
#pragma unroll
                for (int nt = 0; nt < 8; nt++) {
                    int nj = nt >> 1, hh = (nt & 1) * 2;
                    MMA4(c[mi][nt], ah[mi], bh[nj][hh], bh[nj][hh + 1]);
                    MMA4(c[mi][nt], ah[mi], bl[nj][hh], bl[nj][hh + 1]);
                    MMA4(c[mi][nt], al[mi], bh[nj][hh], bh[nj][hh + 1]);
                }
            }
        }
        __syncthreads();
    }

    const int m0 = tileM * 128 + warpM * 32;
    const int n0 = tileN * 128 + warpN * 64;
    const int rq = lane >> 2, cq = (lane & 3) * 2;
#pragma unroll
    for (int mi = 0; mi < 2; mi++) {
#pragma unroll
        for (int nt = 0; nt < 8; nt++) {
            int col = n0 + nt * 8 + cq;
            float2 b2 = *(const float2*)(bias + col);
            int r0 = m0 + mi * 16 + rq;
            float2 o0, o1;
            o0.x = c[mi][nt][0] + b2.x; o0.y = c[mi][nt][1] + b2.y;
            o1.x = c[mi][nt][2] + b2.x; o1.y = c[mi][nt][3] + b2.y;
            *(float2*)(Cm + (size_t)r0 * N + col)       = o0;
            *(float2*)(Cm + (size_t)(r0 + 8) * N + col) = o1;
        }
    }
}

// ---------------------------------------------------------------------------
// RoPE + split: qkv[S,3*HID] -> bf16 hi/lo Q (pre-scaled), K, V in [H][S][D]
// ---------------------------------------------------------------------------
__global__ void rope_split(const float* __restrict__ cosp,
                           const float* __restrict__ sinp)
{
    int idx = blockIdx.x * blockDim.x + threadIdx.x;
    if (idx >= S_ * HID_) return;
    int s   = idx / HID_;
    int col = idx - s * HID_;
    int h   = col / D_;
    int d   = col - h * D_;

    const float* base = g_qkv + (size_t)s * THREE_HID;
    float qv = base[col];
    float kv = base[HID_ + col];
    float vv = base[2 * HID_ + col];

    float cc = cosp[s * D_ + d];
    float sn = sinp[s * D_ + d];

    int off = (d < 40) ? (col + 40) : (col - 40);
    float sgn = (d < 40) ? -1.f : 1.f;
    float qrot = sgn * base[off];
    float krot = sgn * base[HID_ + off];

    const float inv_scale = rsqrtf((float)D_);
    float qf = (qv * cc + qrot * sn) * inv_scale;
    float kf = kv * cc + krot * sn;

    size_t o = (size_t)h * S_ * D_ + (size_t)s * D_ + d;
    __nv_bfloat16 qh = __float2bfloat16(qf);
    __nv_bfloat16 kh = __float2bfloat16(kf);
    __nv_bfloat16 vh = __float2bfloat16(vv);
    g_qhi[o] = qh; g_qlo[o] = __float2bfloat16(qf - __bfloat162float(qh));
    g_khi[o] = kh; g_klo[o] = __float2bfloat16(kf - __bfloat162float(kh));
    g_vhi[o] = vh; g_vlo[o] = __float2bfloat16(vv - __bfloat162float(vh));
}

// ---------------------------------------------------------------------------
// HMMA flash attention. 128q rows/CTA, 64k tiles, 8 warps (16 rows each).
// QK^T and PV both 3-term bf16 split; softmax in C-fragment registers.
// ---------------------------------------------------------------------------
#define ATT_STRIDE 88
#define Q_BYTES (128 * ATT_STRIDE * 2)    // 22528
#define T_BYTES (64 * ATT_STRIDE * 2)     // 11264
#define OFF_QH 0
#define OFF_QL Q_BYTES
#define OFF_KH (2 * Q_BYTES)
#define OFF_KL (2 * Q_BYTES + 2 * T_BYTES)
#define OFF_VH (2 * Q_BYTES + 4 * T_BYTES)
#define OFF_VL (2 * Q_BYTES + 6 * T_BYTES)
#define ATTN_SMEM_BYTES (2 * Q_BYTES + 8 * T_BYTES)   // 135168

__global__ __launch_bounds__(256) void attn_mma()
{
    extern __shared__ char smc[];
    const uint32_t sb = smem_u32(smc);

    const int bx = blockIdx.x;
    const int qt = bx & 7;
    const int h  = (bx >> 3) & 15;
    const int c  = bx >> 7;

    const int tid = threadIdx.x;
    const int lane = tid & 31, w = tid >> 5;
    const int quad = lane >> 3, l8 = lane & 7;

    const size_t hq = (size_t)h * S_ * D_ + (size_t)(c * L_ + qt * 128) * D_;
    const size_t hk = (size_t)h * S_ * D_ + (size_t)(c * L_) * D_;

    // issue Q + KV tile 0 (one group)
    for (int i = tid; i < 1280; i += 256) {
        int row = i / 10, seg = i - row * 10;
        uint32_t off = (uint32_t)(row * ATT_STRIDE + seg * 8) * 2;
        size_t g = hq + (size_t)row * 80 + seg * 8;
        CPA16(sb + OFF_QH + off, g_qhi + g);
        CPA16(sb + OFF_QL + off, g_qlo + g);
    }
    for (int i = tid; i < 640; i += 256) {
        int row = i / 10, seg = i - row * 10;
        uint32_t off = (uint32_t)(row * ATT_STRIDE + seg * 8) * 2;
        size_t g = hk + (size_t)row * 80 + seg * 8;
        CPA16(sb + OFF_KH + off, g_khi + g);
        CPA16(sb + OFF_KL + off, g_klo + g);
        CPA16(sb + OFF_VH + off, g_vhi + g);
        CPA16(sb + OFF_VL + off, g_vlo + g);
    }
    asm volatile("cp.async.commit_group;" ::: "memory");

    float m_a = -1e30f, m_b = -1e30f, l_a = 0.f, l_b = 0.f;
    float out[10][4];
#pragma unroll
    for (int vt = 0; vt < 10; vt++)
#pragma unroll
        for (int r = 0; r < 4; r++) out[vt][r] = 0.f;

    for (int t = 0; t < 16; t++) {
        if (t + 1 < 16) {
            const uint32_t s1 = ((t + 1) & 1) * T_BYTES;
            const size_t tb = hk + (size_t)(t + 1) * 64 * 80;
            for (int i = tid; i < 640; i += 256) {
                int row = i / 10, seg = i - row * 10;
                uint32_t off = (uint32_t)(row * ATT_STRIDE + seg * 8) * 2 + s1;
                size_t g = tb + (size_t)row * 80 + seg * 8;
                CPA16(sb + OFF_KH + off, g_khi + g);
                CPA16(sb + OFF_KL + off, g_klo + g);
                CPA16(sb + OFF_VH + off, g_vhi + g);
                CPA16(sb + OFF_VL + off, g_vlo + g);
            }
            asm volatile("cp.async.commit_group;" ::: "memory");
            asm volatile("cp.async.wait_group 1;" ::: "memory");
        } else {
            asm volatile("cp.async.wait_group 0;" ::: "memory");
        }
        __syncthreads();

        const uint32_t stg = (t & 1) * T_BYTES;
        const uint32_t KHs = sb + OFF_KH + stg;
        const uint32_t KLs = sb + OFF_KL + stg;
        const uint32_t VHs = sb + OFF_VH + stg;
        const uint32_t VLs = sb + OFF_VL + stg;

        // ---- scores ----
        float sc[8][4];
#pragma unroll
        for (int nt = 0; nt < 8; nt++)
#pragma unroll
            for (int r = 0; r < 4; r++) sc[nt][r] = 0.f;

        const int arow = w * 16 + (quad & 1) * 8 + l8;
#pragma unroll
        for (int kk = 0; kk < 5; kk++) {
            uint32_t ah[4], al[4];
            uint32_t aoff = (uint32_t)(arow * ATT_STRIDE + kk * 16 + (quad >> 1) * 8) * 2;
            LDSM4(ah, sb + OFF_QH + aoff);
            LDSM4(al, sb + OFF_QL + aoff);
#pragma unroll
            for (int nj = 0; nj < 4; nj++) {
                uint32_t bh[4], bl[4];
                uint32_t boff = (uint32_t)((nj * 16 + (quad >> 1) * 8 + l8) * ATT_STRIDE
                                           + kk * 16 + (quad & 1) * 8) * 2;
                LDSM4(bh, KHs + boff);
                LDSM4(bl, KLs + boff);
                MMA4(sc[2 * nj],     ah, bh[0], bh[1]);
                MMA4(sc[2 * nj],     ah, bl[0], bl[1]);
                MMA4(sc[2 * nj],     al, bh[0], bh[1]);
                MMA4(sc[2 * nj + 1], ah, bh[2], bh[3]);
                MMA4(sc[2 * nj + 1], ah, bl[2], bl[3]);
                MMA4(sc[2 * nj + 1], al, bh[2], bh[3]);
            }
        }

        // ---- online softmax on fragments (rows lane/4 and lane/4+8) ----
        float mxa = sc[0][0], mxb = sc[0][2];
#pragma unroll
        for (int nt = 0; nt < 8; nt++) {
            mxa = fmaxf(mxa, fmaxf(sc[nt][0], sc[nt][1]));
            mxb = fmaxf(mxb, fmaxf(sc[nt][2], sc[nt][3]));
        }
        mxa = fmaxf(mxa, __shfl_xor_sync(0xffffffffu, mxa, 1));
        mxa = fmaxf(mxa, __shfl_xor_sync(0xffffffffu, mxa, 2));
        mxb = fmaxf(mxb, __shfl_xor_sync(0xffffffffu, mxb, 1));
        mxb = fmaxf(mxb, __shfl_xor_sync(0xffffffffu, mxb, 2));
        float nma = fmaxf(m_a, mxa), nmb = fmaxf(m_b, mxb);
        float ca  = __expf(m_a - nma), cb = __expf(m_b - nmb);
        m_a = nma; m_b = nmb;

        float sa = 0.f, sbv = 0.f;
#pragma unroll
        for (int nt = 0; nt < 8; nt++) {
            sc[nt][0] = __expf(sc[nt][0] - m_a);
            sc[nt][1] = __expf(sc[nt][1] - m_a);
            sc[nt][2] = __expf(sc[nt][2] - m_b);
            sc[nt][3] = __expf(sc[nt][3] - m_b);
            sa  += sc[nt][0] + sc[nt][1];
            sbv += sc[nt][2] + sc[nt][3];
        }
        sa  += __shfl_xor_sync(0xffffffffu, sa, 1);
        sa  += __shfl_xor_sync(0xffffffffu, sa, 2);
        sbv += __shfl_xor_sync(0xffffffffu, sbv, 1);
        sbv += __shfl_xor_sync(0xffffffffu, sbv, 2);
        l_a = l_a * ca + sa;
        l_b = l_b * cb + sbv;

        // ---- pack P into A-fragments (hi + residual lo) ----
        uint32_t Ph[4][4], Pl[4][4];
#pragma unroll
        for (int kk = 0; kk < 4; kk++) {
#pragma unroll
            for (int half = 0; half < 2; half++) {
                int nt = 2 * kk + half;
                uint32_t h0 = pk2(sc[nt][0], sc[nt][1]);
                uint32_t h1 = pk2(sc[nt][2], sc[nt][3]);
                Ph[kk][2 * half + 0] = h0;
                Ph[kk][2 * half + 1] = h1;
                Pl[kk][2 * half + 0] = pk2(sc[nt][0] - lo_of(h0), sc[nt][1] - hi_of(h0));
                Pl[kk][2 * half + 1] = pk2(sc[nt][2] - lo_of(h1), sc[nt][3] - hi_of(h1));
            }
        }

        // ---- rescale O accumulators ----
#pragma unroll
        for (int vt = 0; vt < 10; vt++) {
            out[vt][0] *= ca; out[vt][1] *= ca;
            out[vt][2] *= cb; out[vt][3] *= cb;
        }

        // ---- PV: O += P @ V  (ldmatrix.trans for V) ----
#pragma unroll
        for (int kk = 0; kk < 4; kk++) {
#pragma unroll
            for (int vj = 0; vj < 5; vj++) {
                uint32_t vhf[4], vlf[4];
                uint32_t voff = (uint32_t)((kk * 16 + (quad & 1) * 8 + l8) * ATT_STRIDE
                                           + vj * 16 + (quad >> 1) * 8) * 2;
                LDSM4T(vhf, VHs + voff);
                LDSM4T(vlf, VLs + voff);
                MMA4(out[2 * vj],     Ph[kk], vhf[0], vhf[1]);
                MMA4(out[2 * vj],     Ph[kk], vlf[0], vlf[1]);
                MMA4(out[2 * vj],     Pl[kk], vhf[0], vhf[1]);
                MMA4(out[2 * vj + 1], Ph[kk], vhf[2], vhf[3]);
                MMA4(out[2 * vj + 1], Ph[kk], vlf[2], vlf[3]);
                MMA4(out[2 * vj + 1], Pl[kk], vhf[2], vhf[3]);
            }
        }
        __syncthreads();
    }

    // ---- epilogue: O/l -> bf16 hi/lo ----
    float ila = 1.f / l_a, ilb = 1.f / l_b;
    int ra = c * L_ + qt * 128 + w * 16 + (lane >> 2);
    int colb = h * D_ + (lane & 3) * 2;
#pragma unroll
    for (int vt = 0; vt < 10; vt++) {
        int col = colb + vt * 8;
        float v0 = out[vt][0] * ila, v1 = out[vt][1] * ila;
        uint32_t hp = pk2(v0, v1);
        uint32_t lp = pk2(v0 - lo_of(hp), v1 - hi_of(hp));
        *(uint32_t*)(g_ahi + (size_t)ra * HID_ + col) = hp;
        *(uint32_t*)(g_alo + (size_t)ra * HID_ + col) = lp;
        float v2 = out[vt][2] * ilb, v3 = out[vt][3] * ilb;
        hp = pk2(v2, v3);
        lp = pk2(v2 - lo_of(hp), v3 - hi_of(hp));
        *(uint32_t*)(g_ahi + (size_t)(ra + 8) * HID_ + col) = hp;
        *(uint32_t*)(g_alo + (size_t)(ra + 8) * HID_ + col) = lp;
    }
}

// ---------------------------------------------------------------------------
// Launch pipeline
// ---------------------------------------------------------------------------
extern "C" void kernel_launch(void* const* d_in, const int* in_sizes, int n_in,
                              void* d_out, int out_size)
{
    const float* x     = (const float*)d_in[0];
    const float* cosp  = (const float*)d_in[1];
    const float* sinp  = (const float*)d_in[2];
    const float* Wqkv  = (const float*)d_in[3];
    const float* bqkv  = (const float*)d_in[4];
    const float* Wproj = (const float*)d_in[5];
    const float* bproj = (const float*)d_in[6];
    float* out = (float*)d_out;

    float* qkv_p;
    __nv_bfloat16 *xhi, *xlo, *wqh, *wql, *wph, *wpl, *ahi, *alo;
    cudaGetSymbolAddress((void**)&qkv_p, g_qkv);
    cudaGetSymbolAddress((void**)&xhi, g_xhi);
    cudaGetSymbolAddress((void**)&xlo, g_xlo);
    cudaGetSymbolAddress((void**)&wqh, g_wqt_hi);
    cudaGetSymbolAddress((void**)&wql, g_wqt_lo);
    cudaGetSymbolAddress((void**)&wph, g_wpt_hi);
    cudaGetSymbolAddress((void**)&wpl, g_wpt_lo);
    cudaGetSymbolAddress((void**)&ahi, g_ahi);
    cudaGetSymbolAddress((void**)&alo, g_alo);

    static int attr_set = 0;
    if (!attr_set) {
        cudaFuncSetAttribute(attn_mma,
                             cudaFuncAttributeMaxDynamicSharedMemorySize,
                             ATTN_SMEM_BYTES);
        cudaFuncSetAttribute(mma_gemm_bias,
                             cudaFuncAttributeMaxDynamicSharedMemorySize,
                             GEMM_SMEM_BYTES);
        attr_set = 1;
    }

    split_rows<<<(S_ * HID_ + 255) / 256, 256>>>(x, xhi, xlo, S_ * HID_);
    split_t<<<dim3(THREE_HID / 32, HID_ / 32), dim3(32, 8)>>>(Wqkv, wqh, wql, HID_, THREE_HID);
    split_t<<<dim3(HID_ / 32, HID_ / 32), dim3(32, 8)>>>(Wproj, wph, wpl, HID_, HID_);

    mma_gemm_bias<<<dim3(THREE_HID / 128, S_ / 128), 256, GEMM_SMEM_BYTES>>>(
        xhi, xlo, wqh, wql, bqkv, qkv_p, S_, THREE_HID, HID_);

    rope_split<<<(S_ * HID_ + 255) / 256, 256>>>(cosp, sinp);

    attn_mma<<<C_ * H_ * (L_ / 128), 256, ATTN_SMEM_BYTES>>>();

    mma_gemm_bias<<<dim3(HID_ / 128, S_ / 128), 256, GEMM_SMEM_BYTES>>>(
        ahi, alo, wph, wpl, bproj, out, S_, HID_, HID_);
}